// round 1
// baseline (speedup 1.0000x reference)
#include <cuda_runtime.h>
#include <cuda_bf16.h>
#include <cstdint>
#include <cstddef>

// Problem constants
#define SEQ   2048
#define HID   3584
#define NH    16
#define NKV   8
#define HD    256
#define QKVN  8192            // (16 + 2*8) * 256
#define ATTN  4096            // 16 * 256
#define SCAL  0.0625f         // 256^-0.5

// Scratch (allocation-free rule: device globals)
__device__ float g_qkv[(size_t)SEQ * QKVN];   // 64 MB
__device__ float g_att[(size_t)SEQ * ATTN];   // 32 MB

// ---------------------------------------------------------------------------
// helpers
// ---------------------------------------------------------------------------
__device__ __forceinline__ unsigned f2tf32(float x) {
    unsigned r;
    asm("cvt.rna.tf32.f32 %0, %1;" : "=r"(r) : "f"(x));
    return r;
}

__device__ __forceinline__ void mma_tf32(float* d, const unsigned* a,
                                         const unsigned* b, const float* c) {
    asm volatile(
        "mma.sync.aligned.m16n8k8.row.col.f32.tf32.tf32.f32 "
        "{%0,%1,%2,%3}, {%4,%5,%6,%7}, {%8,%9}, {%10,%11,%12,%13};\n"
        : "=f"(d[0]), "=f"(d[1]), "=f"(d[2]), "=f"(d[3])
        : "r"(a[0]), "r"(a[1]), "r"(a[2]), "r"(a[3]),
          "r"(b[0]), "r"(b[1]),
          "f"(c[0]), "f"(c[1]), "f"(c[2]), "f"(c[3]));
}

// ---------------------------------------------------------------------------
// GEMM: C[M,N] = A[M,K] * B[N,K]^T   (both operands row-major, K contiguous)
// 128x128 block tile, BK=16, 256 threads, 8 warps in 2x4 (warp tile 64x32).
// ---------------------------------------------------------------------------
#define GLDA 20   // padded smem row stride (16 + 4) -> conflict-free frag loads

__global__ void __launch_bounds__(256)
gemm_abt_tf32(const float* __restrict__ A, const float* __restrict__ B,
              float* __restrict__ C, int M, int N, int K) {
    __shared__ unsigned As[2][128 * GLDA];
    __shared__ unsigned Bs[2][128 * GLDA];

    const int tid  = threadIdx.x;
    const int m0   = blockIdx.x * 128;
    const int n0   = blockIdx.y * 128;
    const int wid  = tid >> 5;
    const int lane = tid & 31;
    const int wm   = (wid >> 2) * 64;   // 0 / 64
    const int wn   = (wid & 3) * 32;    // 0..96
    const int tg   = lane >> 2;         // 0..7
    const int tq   = lane & 3;          // 0..3

    float acc[4][4][4];
#pragma unroll
    for (int mi = 0; mi < 4; mi++)
#pragma unroll
        for (int ni = 0; ni < 4; ni++)
#pragma unroll
            for (int e = 0; e < 4; e++) acc[mi][ni][e] = 0.f;

    const int lr = tid >> 2;           // 0..63 (two row passes: lr, lr+64)
    const int lc = (tid & 3) * 4;      // 0,4,8,12
    const float* pA = A + (size_t)(m0 + lr) * K + lc;
    const float* pB = B + (size_t)(n0 + lr) * K + lc;
    const int NK = K >> 4;

    // initial tile -> smem buf 0
    {
        float4 a0 = *(const float4*)pA;
        float4 a1 = *(const float4*)(pA + (size_t)64 * K);
        float4 b0 = *(const float4*)pB;
        float4 b1 = *(const float4*)(pB + (size_t)64 * K);
        unsigned* da0 = &As[0][lr * GLDA + lc];
        unsigned* da1 = &As[0][(lr + 64) * GLDA + lc];
        unsigned* db0 = &Bs[0][lr * GLDA + lc];
        unsigned* db1 = &Bs[0][(lr + 64) * GLDA + lc];
        da0[0]=f2tf32(a0.x); da0[1]=f2tf32(a0.y); da0[2]=f2tf32(a0.z); da0[3]=f2tf32(a0.w);
        da1[0]=f2tf32(a1.x); da1[1]=f2tf32(a1.y); da1[2]=f2tf32(a1.z); da1[3]=f2tf32(a1.w);
        db0[0]=f2tf32(b0.x); db0[1]=f2tf32(b0.y); db0[2]=f2tf32(b0.z); db0[3]=f2tf32(b0.w);
        db1[0]=f2tf32(b1.x); db1[1]=f2tf32(b1.y); db1[2]=f2tf32(b1.z); db1[3]=f2tf32(b1.w);
    }
    __syncthreads();

    for (int kt = 0; kt < NK; ++kt) {
        const int buf = kt & 1;
        float4 na0, na1, nb0, nb1;
        const bool more = (kt + 1 < NK);
        if (more) {
            const float* qA = pA + (size_t)(kt + 1) * 16;
            const float* qB = pB + (size_t)(kt + 1) * 16;
            na0 = *(const float4*)qA;
            na1 = *(const float4*)(qA + (size_t)64 * K);
            nb0 = *(const float4*)qB;
            nb1 = *(const float4*)(qB + (size_t)64 * K);
        }
#pragma unroll
        for (int kk = 0; kk < 16; kk += 8) {
            unsigned af[4][4], bf[4][2];
#pragma unroll
            for (int mi = 0; mi < 4; mi++) {
                const int r = wm + mi * 16 + tg;
                af[mi][0] = As[buf][r * GLDA + kk + tq];
                af[mi][1] = As[buf][(r + 8) * GLDA + kk + tq];
                af[mi][2] = As[buf][r * GLDA + kk + tq + 4];
                af[mi][3] = As[buf][(r + 8) * GLDA + kk + tq + 4];
            }
#pragma unroll
            for (int ni = 0; ni < 4; ni++) {
                const int r = wn + ni * 8 + tg;
                bf[ni][0] = Bs[buf][r * GLDA + kk + tq];
                bf[ni][1] = Bs[buf][r * GLDA + kk + tq + 4];
            }
#pragma unroll
            for (int mi = 0; mi < 4; mi++)
#pragma unroll
                for (int ni = 0; ni < 4; ni++)
                    mma_tf32(acc[mi][ni], af[mi], bf[ni], acc[mi][ni]);
        }
        if (more) {
            const int nb = buf ^ 1;
            unsigned* da0 = &As[nb][lr * GLDA + lc];
            unsigned* da1 = &As[nb][(lr + 64) * GLDA + lc];
            unsigned* db0 = &Bs[nb][lr * GLDA + lc];
            unsigned* db1 = &Bs[nb][(lr + 64) * GLDA + lc];
            da0[0]=f2tf32(na0.x); da0[1]=f2tf32(na0.y); da0[2]=f2tf32(na0.z); da0[3]=f2tf32(na0.w);
            da1[0]=f2tf32(na1.x); da1[1]=f2tf32(na1.y); da1[2]=f2tf32(na1.z); da1[3]=f2tf32(na1.w);
            db0[0]=f2tf32(nb0.x); db0[1]=f2tf32(nb0.y); db0[2]=f2tf32(nb0.z); db0[3]=f2tf32(nb0.w);
            db1[0]=f2tf32(nb1.x); db1[1]=f2tf32(nb1.y); db1[2]=f2tf32(nb1.z); db1[3]=f2tf32(nb1.w);
        }
        __syncthreads();
    }

    // epilogue
#pragma unroll
    for (int mi = 0; mi < 4; mi++) {
#pragma unroll
        for (int ni = 0; ni < 4; ni++) {
            const int r = m0 + wm + mi * 16 + tg;
            const int c = n0 + wn + ni * 8 + tq * 2;
            float2 v0 = make_float2(acc[mi][ni][0], acc[mi][ni][1]);
            float2 v1 = make_float2(acc[mi][ni][2], acc[mi][ni][3]);
            *(float2*)&C[(size_t)r * N + c]       = v0;
            *(float2*)&C[(size_t)(r + 8) * N + c] = v1;
        }
    }
}

// ---------------------------------------------------------------------------
// RoPE + q-scaling on g_qkv columns [0, 6144)   (16 q heads + 8 k heads)
// ---------------------------------------------------------------------------
__global__ void rope_kernel(float* __restrict__ qkv,
                            const float* __restrict__ fcos,
                            const float* __restrict__ fsin) {
    const int idx = blockIdx.x * blockDim.x + threadIdx.x;   // exact multiple
    const int d = idx & 127;
    const int h = (idx >> 7) % 24;
    const int s = idx / (24 * 128);
    const size_t base = (size_t)s * QKVN + h * 256;
    float xr = qkv[base + d];
    float xi = qkv[base + 128 + d];
    const float c  = fcos[s * 128 + d];
    const float sn = fsin[s * 128 + d];
    float nr = xr * c - xi * sn;
    float ni = xr * sn + xi * c;
    if (h < NH) { nr *= SCAL; ni *= SCAL; }
    qkv[base + d]       = nr;
    qkv[base + 128 + d] = ni;
}

// ---------------------------------------------------------------------------
// Flash attention with tanh softcap.
// Block: 128 threads (4 warps), 64 q-rows, one head. Grid: (32 qtiles, 16 heads).
// ---------------------------------------------------------------------------
#define LDQ 260   // 256 + 4 pad
#define LDP 68    // 64 + 4 pad
#define SMEM_ATT ((3 * 64 * LDQ + 64 * LDP) * 4)   // 217088 bytes

__global__ void __launch_bounds__(128)
attn_kernel() {
    extern __shared__ unsigned sm[];
    unsigned* Qs = sm;
    unsigned* Ks = Qs + 64 * LDQ;
    unsigned* Vs = Ks + 64 * LDQ;
    unsigned* Ps = Vs + 64 * LDQ;

    const int tid  = threadIdx.x;
    const int wid  = tid >> 5;
    const int lane = tid & 31;
    const int tg   = lane >> 2;
    const int tq   = lane & 3;
    const int wm   = wid * 16;

    const int qt = (int)(gridDim.x - 1) - (int)blockIdx.x;  // heavy tiles first
    const int q0 = qt * 64;
    const int h  = blockIdx.y;
    const int kh = h >> 1;
    const int qcb = h * 256;
    const int kcb = 4096 + kh * 256;
    const int vcb = 6144 + kh * 256;

    // load Q tile (tf32)
    for (int i = tid; i < 64 * 64; i += 128) {
        const int r = i >> 6, c4 = (i & 63) * 4;
        float4 v = *(const float4*)&g_qkv[(size_t)(q0 + r) * QKVN + qcb + c4];
        unsigned* d = &Qs[r * LDQ + c4];
        d[0] = f2tf32(v.x); d[1] = f2tf32(v.y); d[2] = f2tf32(v.z); d[3] = f2tf32(v.w);
    }

    float o[32][4];
#pragma unroll
    for (int nf = 0; nf < 32; nf++)
#pragma unroll
        for (int e = 0; e < 4; e++) o[nf][e] = 0.f;
    float mrow[2] = {-1e30f, -1e30f};
    float lrow[2] = {0.f, 0.f};

    for (int kt = 0; kt <= qt; ++kt) {
        __syncthreads();   // protects K/V from previous iteration's readers
        const int r0g = kt * 64;
        for (int i = tid; i < 64 * 64; i += 128) {
            const int r = i >> 6, c4 = (i & 63) * 4;
            const size_t rowb = (size_t)(r0g + r) * QKVN;
            float4 kv = *(const float4*)&g_qkv[rowb + kcb + c4];
            float4 vv = *(const float4*)&g_qkv[rowb + vcb + c4];
            unsigned* dk = &Ks[r * LDQ + c4];
            unsigned* dv = &Vs[r * LDQ + c4];
            dk[0]=f2tf32(kv.x); dk[1]=f2tf32(kv.y); dk[2]=f2tf32(kv.z); dk[3]=f2tf32(kv.w);
            dv[0]=f2tf32(vv.x); dv[1]=f2tf32(vv.y); dv[2]=f2tf32(vv.z); dv[3]=f2tf32(vv.w);
        }
        __syncthreads();

        // S = Q K^T  (64 cols per warp-row band of 16 q rows)
        float s[8][4];
#pragma unroll
        for (int nf = 0; nf < 8; nf++)
#pragma unroll
            for (int e = 0; e < 4; e++) s[nf][e] = 0.f;

        for (int ks = 0; ks < 32; ++ks) {
            const int kk = ks * 8;
            unsigned a[4];
            const int ra = (wm + tg) * LDQ + kk + tq;
            a[0] = Qs[ra];
            a[1] = Qs[ra + 8 * LDQ];
            a[2] = Qs[ra + 4];
            a[3] = Qs[ra + 8 * LDQ + 4];
#pragma unroll
            for (int nf = 0; nf < 8; nf++) {
                unsigned b[2];
                const int rb = (nf * 8 + tg) * LDQ + kk + tq;
                b[0] = Ks[rb];
                b[1] = Ks[rb + 4];
                mma_tf32(s[nf], a, b, s[nf]);
            }
        }

        // softcap + causal mask + online softmax
        const bool diag = (kt == qt);
        const int grow0 = q0 + wm + tg;
        float mx[2] = {-1e30f, -1e30f};
#pragma unroll
        for (int nf = 0; nf < 8; nf++) {
#pragma unroll
            for (int e = 0; e < 4; e++) {
                float x = s[nf][e];
                const float ex = __expf(x * 0.04f);            // 2/SOFTCAP
                x = 50.f * (ex - 1.f) / (ex + 1.f);
                if (diag) {
                    const int col = kt * 64 + nf * 8 + tq * 2 + (e & 1);
                    const int row = grow0 + ((e >> 1) << 3);
                    if (col > row) x = -1e30f;
                }
                s[nf][e] = x;
                mx[e >> 1] = fmaxf(mx[e >> 1], x);
            }
        }
        mx[0] = fmaxf(mx[0], __shfl_xor_sync(0xffffffffu, mx[0], 1));
        mx[0] = fmaxf(mx[0], __shfl_xor_sync(0xffffffffu, mx[0], 2));
        mx[1] = fmaxf(mx[1], __shfl_xor_sync(0xffffffffu, mx[1], 1));
        mx[1] = fmaxf(mx[1], __shfl_xor_sync(0xffffffffu, mx[1], 2));

        const float nm0 = fmaxf(mrow[0], mx[0]);
        const float nm1 = fmaxf(mrow[1], mx[1]);
        const float al0 = __expf(mrow[0] - nm0);
        const float al1 = __expf(mrow[1] - nm1);

        float sum[2] = {0.f, 0.f};
#pragma unroll
        for (int nf = 0; nf < 8; nf++) {
#pragma unroll
            for (int e = 0; e < 4; e++) {
                const float nm = (e < 2) ? nm0 : nm1;
                const float p = __expf(s[nf][e] - nm);
                sum[e >> 1] += p;
                const int prow = wm + tg + ((e >> 1) << 3);
                Ps[prow * LDP + nf * 8 + tq * 2 + (e & 1)] = f2tf32(p);
            }
        }
        sum[0] += __shfl_xor_sync(0xffffffffu, sum[0], 1);
        sum[0] += __shfl_xor_sync(0xffffffffu, sum[0], 2);
        sum[1] += __shfl_xor_sync(0xffffffffu, sum[1], 1);
        sum[1] += __shfl_xor_sync(0xffffffffu, sum[1], 2);

        lrow[0] = lrow[0] * al0 + sum[0];  mrow[0] = nm0;
        lrow[1] = lrow[1] * al1 + sum[1];  mrow[1] = nm1;

#pragma unroll
        for (int nf = 0; nf < 32; nf++) {
            o[nf][0] *= al0; o[nf][1] *= al0;
            o[nf][2] *= al1; o[nf][3] *= al1;
        }
        __syncwarp();   // P smem visibility within the warp

        // O += P V
#pragma unroll
        for (int ks = 0; ks < 8; ++ks) {
            const int kk = ks * 8;
            unsigned a[4];
            const int ra = (wm + tg) * LDP + kk + tq;
            a[0] = Ps[ra];
            a[1] = Ps[ra + 8 * LDP];
            a[2] = Ps[ra + 4];
            a[3] = Ps[ra + 8 * LDP + 4];
#pragma unroll
            for (int nf = 0; nf < 32; nf++) {
                unsigned b[2];
                const int rb = (kk + tq) * LDQ + nf * 8 + tg;
                b[0] = Vs[rb];
                b[1] = Vs[rb + 4 * LDQ];
                mma_tf32(o[nf], a, b, o[nf]);
            }
        }
    }

    // finalize + store
    const float i0 = 1.f / lrow[0];
    const float i1 = 1.f / lrow[1];
    const size_t r0 = (size_t)(q0 + wm + tg);
#pragma unroll
    for (int nf = 0; nf < 32; nf++) {
        const int c = qcb + nf * 8 + tq * 2;
        *(float2*)&g_att[r0 * ATTN + c]       = make_float2(o[nf][0] * i0, o[nf][1] * i0);
        *(float2*)&g_att[(r0 + 8) * ATTN + c] = make_float2(o[nf][2] * i1, o[nf][3] * i1);
    }
}

// ---------------------------------------------------------------------------
// launch
// ---------------------------------------------------------------------------
extern "C" void kernel_launch(void* const* d_in, const int* in_sizes, int n_in,
                              void* d_out, int out_size) {
    const float* hidden = (const float*)d_in[0];
    const float* fcos   = (const float*)d_in[1];
    const float* fsin   = (const float*)d_in[2];
    /* d_in[3] = mask: causal mask is generated analytically */
    const float* qkv_w  = (const float*)d_in[4];
    const float* o_w    = (const float*)d_in[5];
    float* out = (float*)d_out;

    cudaFuncSetAttribute(attn_kernel,
                         cudaFuncAttributeMaxDynamicSharedMemorySize, SMEM_ATT);

    float* qkv = nullptr;
    float* att = nullptr;
    cudaGetSymbolAddress((void**)&qkv, g_qkv);
    cudaGetSymbolAddress((void**)&att, g_att);

    // 1) QKV projection: [2048,3584] x [8192,3584]^T -> [2048,8192]
    gemm_abt_tf32<<<dim3(SEQ / 128, QKVN / 128), 256>>>(hidden, qkv_w, qkv,
                                                        SEQ, QKVN, HID);
    // 2) RoPE on q+k heads, + q scaling
    rope_kernel<<<(SEQ * 24 * 128) / 256, 256>>>(qkv, fcos, fsin);
    // 3) softcapped causal flash attention
    attn_kernel<<<dim3(SEQ / 64, NH), 128, SMEM_ATT>>>();
    // 4) output projection: [2048,4096] x [3584,4096]^T -> [2048,3584]
    gemm_abt_tf32<<<dim3(SEQ / 128, HID / 128), 256>>>(att, o_w, out,
                                                       SEQ, HID, ATTN);
}

// round 2
// speedup vs baseline: 1.0285x; 1.0285x over previous
#include <cuda_runtime.h>
#include <cuda_bf16.h>
#include <cstdint>
#include <cstddef>

// Problem constants
#define SEQ   2048
#define HID   3584
#define NH    16
#define NKV   8
#define HD    256
#define QKVN  8192            // (16 + 2*8) * 256
#define ATTN  4096            // 16 * 256
#define SCAL  0.0625f         // 256^-0.5

// Scratch (allocation-free rule: device globals)
__device__ float g_qkv[(size_t)SEQ * QKVN];   // 64 MB
__device__ float g_att[(size_t)SEQ * ATTN];   // 32 MB

// ---------------------------------------------------------------------------
// helpers
// ---------------------------------------------------------------------------
__device__ __forceinline__ unsigned f2tf32(float x) {
    unsigned r;
    asm("cvt.rna.tf32.f32 %0, %1;" : "=r"(r) : "f"(x));
    return r;
}

__device__ __forceinline__ void mma_tf32(float* d, const unsigned* a,
                                         const unsigned* b, const float* c) {
    asm volatile(
        "mma.sync.aligned.m16n8k8.row.col.f32.tf32.tf32.f32 "
        "{%0,%1,%2,%3}, {%4,%5,%6,%7}, {%8,%9}, {%10,%11,%12,%13};\n"
        : "=f"(d[0]), "=f"(d[1]), "=f"(d[2]), "=f"(d[3])
        : "r"(a[0]), "r"(a[1]), "r"(a[2]), "r"(a[3]),
          "r"(b[0]), "r"(b[1]),
          "f"(c[0]), "f"(c[1]), "f"(c[2]), "f"(c[3]));
}

// ---------------------------------------------------------------------------
// GEMM: C[M,N] = A[M,K] * B[N,K]^T   (both operands row-major, K contiguous)
// 128x128 block tile, BK=16, 256 threads, 8 warps in 2x4 (warp tile 64x32).
// ---------------------------------------------------------------------------
#define GLDA 20   // padded smem row stride (16 + 4) -> conflict-free frag loads

__global__ void __launch_bounds__(256)
gemm_abt_tf32(const float* __restrict__ A, const float* __restrict__ B,
              float* __restrict__ C, int M, int N, int K) {
    __shared__ unsigned As[2][128 * GLDA];
    __shared__ unsigned Bs[2][128 * GLDA];

    const int tid  = threadIdx.x;
    const int m0   = blockIdx.x * 128;
    const int n0   = blockIdx.y * 128;
    const int wid  = tid >> 5;
    const int lane = tid & 31;
    const int wm   = (wid >> 2) * 64;   // 0 / 64
    const int wn   = (wid & 3) * 32;    // 0..96
    const int tg   = lane >> 2;         // 0..7
    const int tq   = lane & 3;          // 0..3

    float acc[4][4][4];
#pragma unroll
    for (int mi = 0; mi < 4; mi++)
#pragma unroll
        for (int ni = 0; ni < 4; ni++)
#pragma unroll
            for (int e = 0; e < 4; e++) acc[mi][ni][e] = 0.f;

    const int lr = tid >> 2;           // 0..63 (two row passes: lr, lr+64)
    const int lc = (tid & 3) * 4;      // 0,4,8,12
    const float* pA = A + (size_t)(m0 + lr) * K + lc;
    const float* pB = B + (size_t)(n0 + lr) * K + lc;
    const int NK = K >> 4;

    // initial tile -> smem buf 0
    {
        float4 a0 = *(const float4*)pA;
        float4 a1 = *(const float4*)(pA + (size_t)64 * K);
        float4 b0 = *(const float4*)pB;
        float4 b1 = *(const float4*)(pB + (size_t)64 * K);
        unsigned* da0 = &As[0][lr * GLDA + lc];
        unsigned* da1 = &As[0][(lr + 64) * GLDA + lc];
        unsigned* db0 = &Bs[0][lr * GLDA + lc];
        unsigned* db1 = &Bs[0][(lr + 64) * GLDA + lc];
        da0[0]=f2tf32(a0.x); da0[1]=f2tf32(a0.y); da0[2]=f2tf32(a0.z); da0[3]=f2tf32(a0.w);
        da1[0]=f2tf32(a1.x); da1[1]=f2tf32(a1.y); da1[2]=f2tf32(a1.z); da1[3]=f2tf32(a1.w);
        db0[0]=f2tf32(b0.x); db0[1]=f2tf32(b0.y); db0[2]=f2tf32(b0.z); db0[3]=f2tf32(b0.w);
        db1[0]=f2tf32(b1.x); db1[1]=f2tf32(b1.y); db1[2]=f2tf32(b1.z); db1[3]=f2tf32(b1.w);
    }
    __syncthreads();

    for (int kt = 0; kt < NK; ++kt) {
        const int buf = kt & 1;
        float4 na0, na1, nb0, nb1;
        const bool more = (kt + 1 < NK);
        if (more) {
            const float* qA = pA + (size_t)(kt + 1) * 16;
            const float* qB = pB + (size_t)(kt + 1) * 16;
            na0 = *(const float4*)qA;
            na1 = *(const float4*)(qA + (size_t)64 * K);
            nb0 = *(const float4*)qB;
            nb1 = *(const float4*)(qB + (size_t)64 * K);
        }
#pragma unroll
        for (int kk = 0; kk < 16; kk += 8) {
            unsigned af[4][4], bf[4][2];
#pragma unroll
            for (int mi = 0; mi < 4; mi++) {
                const int r = wm + mi * 16 + tg;
                af[mi][0] = As[buf][r * GLDA + kk + tq];
                af[mi][1] = As[buf][(r + 8) * GLDA + kk + tq];
                af[mi][2] = As[buf][r * GLDA + kk + tq + 4];
                af[mi][3] = As[buf][(r + 8) * GLDA + kk + tq + 4];
            }
#pragma unroll
            for (int ni = 0; ni < 4; ni++) {
                const int r = wn + ni * 8 + tg;
                bf[ni][0] = Bs[buf][r * GLDA + kk + tq];
                bf[ni][1] = Bs[buf][r * GLDA + kk + tq + 4];
            }
#pragma unroll
            for (int mi = 0; mi < 4; mi++)
#pragma unroll
                for (int ni = 0; ni < 4; ni++)
                    mma_tf32(acc[mi][ni], af[mi], bf[ni], acc[mi][ni]);
        }
        if (more) {
            const int nb = buf ^ 1;
            unsigned* da0 = &As[nb][lr * GLDA + lc];
            unsigned* da1 = &As[nb][(lr + 64) * GLDA + lc];
            unsigned* db0 = &Bs[nb][lr * GLDA + lc];
            unsigned* db1 = &Bs[nb][(lr + 64) * GLDA + lc];
            da0[0]=f2tf32(na0.x); da0[1]=f2tf32(na0.y); da0[2]=f2tf32(na0.z); da0[3]=f2tf32(na0.w);
            da1[0]=f2tf32(na1.x); da1[1]=f2tf32(na1.y); da1[2]=f2tf32(na1.z); da1[3]=f2tf32(na1.w);
            db0[0]=f2tf32(nb0.x); db0[1]=f2tf32(nb0.y); db0[2]=f2tf32(nb0.z); db0[3]=f2tf32(nb0.w);
            db1[0]=f2tf32(nb1.x); db1[1]=f2tf32(nb1.y); db1[2]=f2tf32(nb1.z); db1[3]=f2tf32(nb1.w);
        }
        __syncthreads();
    }

    // epilogue
#pragma unroll
    for (int mi = 0; mi < 4; mi++) {
#pragma unroll
        for (int ni = 0; ni < 4; ni++) {
            const int r = m0 + wm + mi * 16 + tg;
            const int c = n0 + wn + ni * 8 + tq * 2;
            float2 v0 = make_float2(acc[mi][ni][0], acc[mi][ni][1]);
            float2 v1 = make_float2(acc[mi][ni][2], acc[mi][ni][3]);
            *(float2*)&C[(size_t)r * N + c]       = v0;
            *(float2*)&C[(size_t)(r + 8) * N + c] = v1;
        }
    }
}

// ---------------------------------------------------------------------------
// RoPE + q-scaling on g_qkv columns [0, 6144)   (16 q heads + 8 k heads)
// ---------------------------------------------------------------------------
__global__ void rope_kernel(float* __restrict__ qkv,
                            const float* __restrict__ fcos,
                            const float* __restrict__ fsin) {
    const int idx = blockIdx.x * blockDim.x + threadIdx.x;   // exact multiple
    const int d = idx & 127;
    const int h = (idx >> 7) % 24;
    const int s = idx / (24 * 128);
    const size_t base = (size_t)s * QKVN + h * 256;
    float xr = qkv[base + d];
    float xi = qkv[base + 128 + d];
    const float c  = fcos[s * 128 + d];
    const float sn = fsin[s * 128 + d];
    float nr = xr * c - xi * sn;
    float ni = xr * sn + xi * c;
    if (h < NH) { nr *= SCAL; ni *= SCAL; }
    qkv[base + d]       = nr;
    qkv[base + 128 + d] = ni;
}

// ---------------------------------------------------------------------------
// Flash attention with tanh softcap, v2.
// Block: 256 threads (8 warps), 64 q-rows, one head. Grid: (32 qtiles, 16 heads).
// Warp (band, chalf): band = wid>>1 owns 16 q-rows; chalf = wid&1 owns a
//   32-col half of S (QK stage) and a 128-d half of O (PV stage).
// Row max/sum exchanged across the two chalf warps through small smem arrays.
// ---------------------------------------------------------------------------
#define LDQ 260   // 256 + 4 pad
#define LDP 68    // 64 + 4 pad
// words: 3*64*LDQ (Q,K,V) + 64*LDP (P) + 128 (pmax) + 128 (psum)
#define SMEM_ATT ((3 * 64 * LDQ + 64 * LDP + 256) * 4)   // 218112 bytes

__global__ void __launch_bounds__(256)
attn_kernel() {
    extern __shared__ unsigned sm[];
    unsigned* Qs = sm;
    unsigned* Ks = Qs + 64 * LDQ;
    unsigned* Vs = Ks + 64 * LDQ;
    unsigned* Ps = Vs + 64 * LDQ;
    float* pmax = (float*)(Ps + 64 * LDP);   // [2][64]
    float* psum = pmax + 128;                // [2][64]

    const int tid   = threadIdx.x;
    const int wid   = tid >> 5;
    const int lane  = tid & 31;
    const int tg    = lane >> 2;
    const int tq    = lane & 3;
    const int band  = wid >> 1;       // 0..3
    const int chalf = wid & 1;        // 0..1
    const int wm    = band * 16;

    const int qt = (int)(gridDim.x - 1) - (int)blockIdx.x;  // heavy tiles first
    const int q0 = qt * 64;
    const int h  = blockIdx.y;
    const int kh = h >> 1;
    const int qcb = h * 256;
    const int kcb = 4096 + kh * 256;
    const int vcb = 6144 + kh * 256;

    // load Q tile (tf32)
    for (int i = tid; i < 64 * 64; i += 256) {
        const int r = i >> 6, c4 = (i & 63) * 4;
        float4 v = *(const float4*)&g_qkv[(size_t)(q0 + r) * QKVN + qcb + c4];
        unsigned* d = &Qs[r * LDQ + c4];
        d[0] = f2tf32(v.x); d[1] = f2tf32(v.y); d[2] = f2tf32(v.z); d[3] = f2tf32(v.w);
    }

    float o[16][4];
#pragma unroll
    for (int nf = 0; nf < 16; nf++)
#pragma unroll
        for (int e = 0; e < 4; e++) o[nf][e] = 0.f;
    float mrow[2] = {-1e30f, -1e30f};
    float lrow[2] = {0.f, 0.f};

    const int cb = chalf * 32;    // S-column base for this warp
    const int db = chalf * 128;   // O d-column base for this warp

    for (int kt = 0; kt <= qt; ++kt) {
        __syncthreads();   // protect K/V/P/partials from previous iteration
        const int r0g = kt * 64;
        for (int i = tid; i < 64 * 64; i += 256) {
            const int r = i >> 6, c4 = (i & 63) * 4;
            const size_t rowb = (size_t)(r0g + r) * QKVN;
            float4 kv = *(const float4*)&g_qkv[rowb + kcb + c4];
            float4 vv = *(const float4*)&g_qkv[rowb + vcb + c4];
            unsigned* dk = &Ks[r * LDQ + c4];
            unsigned* dv = &Vs[r * LDQ + c4];
            dk[0]=f2tf32(kv.x); dk[1]=f2tf32(kv.y); dk[2]=f2tf32(kv.z); dk[3]=f2tf32(kv.w);
            dv[0]=f2tf32(vv.x); dv[1]=f2tf32(vv.y); dv[2]=f2tf32(vv.z); dv[3]=f2tf32(vv.w);
        }
        __syncthreads();

        // S = Q K^T  (16 rows x 32 cols per warp)
        float s[4][4];
#pragma unroll
        for (int nf = 0; nf < 4; nf++)
#pragma unroll
            for (int e = 0; e < 4; e++) s[nf][e] = 0.f;

        for (int ks = 0; ks < 32; ++ks) {
            const int kk = ks * 8;
            unsigned a[4];
            const int ra = (wm + tg) * LDQ + kk + tq;
            a[0] = Qs[ra];
            a[1] = Qs[ra + 8 * LDQ];
            a[2] = Qs[ra + 4];
            a[3] = Qs[ra + 8 * LDQ + 4];
#pragma unroll
            for (int nf = 0; nf < 4; nf++) {
                unsigned b[2];
                const int rb = (cb + nf * 8 + tg) * LDQ + kk + tq;
                b[0] = Ks[rb];
                b[1] = Ks[rb + 4];
                mma_tf32(s[nf], a, b, s[nf]);
            }
        }

        // softcap + causal mask + partial row max
        const bool diag = (kt == qt);
        const int grow0 = q0 + wm + tg;
        float mx[2] = {-1e30f, -1e30f};
#pragma unroll
        for (int nf = 0; nf < 4; nf++) {
#pragma unroll
            for (int e = 0; e < 4; e++) {
                float x = s[nf][e];
                const float ex = __expf(x * 0.04f);            // 2/SOFTCAP
                x = 50.f * (ex - 1.f) / (ex + 1.f);
                if (diag) {
                    const int col = kt * 64 + cb + nf * 8 + tq * 2 + (e & 1);
                    const int row = grow0 + ((e >> 1) << 3);
                    if (col > row) x = -1e30f;
                }
                s[nf][e] = x;
                mx[e >> 1] = fmaxf(mx[e >> 1], x);
            }
        }
        mx[0] = fmaxf(mx[0], __shfl_xor_sync(0xffffffffu, mx[0], 1));
        mx[0] = fmaxf(mx[0], __shfl_xor_sync(0xffffffffu, mx[0], 2));
        mx[1] = fmaxf(mx[1], __shfl_xor_sync(0xffffffffu, mx[1], 1));
        mx[1] = fmaxf(mx[1], __shfl_xor_sync(0xffffffffu, mx[1], 2));
        if (tq == 0) {
            pmax[chalf * 64 + wm + tg]     = mx[0];
            pmax[chalf * 64 + wm + tg + 8] = mx[1];
        }
        __syncthreads();

        // combined new max -> probabilities + partial sums + P tile
        const float tm0 = fmaxf(pmax[wm + tg],     pmax[64 + wm + tg]);
        const float tm1 = fmaxf(pmax[wm + tg + 8], pmax[64 + wm + tg + 8]);
        const float nm0 = fmaxf(mrow[0], tm0);
        const float nm1 = fmaxf(mrow[1], tm1);
        const float al0 = __expf(mrow[0] - nm0);
        const float al1 = __expf(mrow[1] - nm1);

        float sum[2] = {0.f, 0.f};
#pragma unroll
        for (int nf = 0; nf < 4; nf++) {
#pragma unroll
            for (int e = 0; e < 4; e++) {
                const float nm = (e < 2) ? nm0 : nm1;
                const float p = __expf(s[nf][e] - nm);
                sum[e >> 1] += p;
                const int prow = wm + tg + ((e >> 1) << 3);
                Ps[prow * LDP + cb + nf * 8 + tq * 2 + (e & 1)] = f2tf32(p);
            }
        }
        sum[0] += __shfl_xor_sync(0xffffffffu, sum[0], 1);
        sum[0] += __shfl_xor_sync(0xffffffffu, sum[0], 2);
        sum[1] += __shfl_xor_sync(0xffffffffu, sum[1], 1);
        sum[1] += __shfl_xor_sync(0xffffffffu, sum[1], 2);
        if (tq == 0) {
            psum[chalf * 64 + wm + tg]     = sum[0];
            psum[chalf * 64 + wm + tg + 8] = sum[1];
        }
        __syncthreads();   // P + psum visible to both chalf warps

        lrow[0] = lrow[0] * al0 + psum[wm + tg]     + psum[64 + wm + tg];
        lrow[1] = lrow[1] * al1 + psum[wm + tg + 8] + psum[64 + wm + tg + 8];
        mrow[0] = nm0;
        mrow[1] = nm1;

#pragma unroll
        for (int nf = 0; nf < 16; nf++) {
            o[nf][0] *= al0; o[nf][1] *= al0;
            o[nf][2] *= al1; o[nf][3] *= al1;
        }

        // O += P V   (16 rows x 128 d-cols per warp, k = 64)
#pragma unroll
        for (int ks = 0; ks < 8; ++ks) {
            const int kk = ks * 8;
            unsigned a[4];
            const int ra = (wm + tg) * LDP + kk + tq;
            a[0] = Ps[ra];
            a[1] = Ps[ra + 8 * LDP];
            a[2] = Ps[ra + 4];
            a[3] = Ps[ra + 8 * LDP + 4];
#pragma unroll
            for (int nf = 0; nf < 16; nf++) {
                unsigned b[2];
                const int rb = (kk + tq) * LDQ + db + nf * 8 + tg;
                b[0] = Vs[rb];
                b[1] = Vs[rb + 4 * LDQ];
                mma_tf32(o[nf], a, b, o[nf]);
            }
        }
    }

    // finalize + store
    const float i0 = 1.f / lrow[0];
    const float i1 = 1.f / lrow[1];
    const size_t r0 = (size_t)(q0 + wm + tg);
#pragma unroll
    for (int nf = 0; nf < 16; nf++) {
        const int c = qcb + db + nf * 8 + tq * 2;
        *(float2*)&g_att[r0 * ATTN + c]       = make_float2(o[nf][0] * i0, o[nf][1] * i0);
        *(float2*)&g_att[(r0 + 8) * ATTN + c] = make_float2(o[nf][2] * i1, o[nf][3] * i1);
    }
}

// ---------------------------------------------------------------------------
// launch
// ---------------------------------------------------------------------------
extern "C" void kernel_launch(void* const* d_in, const int* in_sizes, int n_in,
                              void* d_out, int out_size) {
    const float* hidden = (const float*)d_in[0];
    const float* fcos   = (const float*)d_in[1];
    const float* fsin   = (const float*)d_in[2];
    /* d_in[3] = mask: causal mask is generated analytically */
    const float* qkv_w  = (const float*)d_in[4];
    const float* o_w    = (const float*)d_in[5];
    float* out = (float*)d_out;

    cudaFuncSetAttribute(attn_kernel,
                         cudaFuncAttributeMaxDynamicSharedMemorySize, SMEM_ATT);

    float* qkv = nullptr;
    float* att = nullptr;
    cudaGetSymbolAddress((void**)&qkv, g_qkv);
    cudaGetSymbolAddress((void**)&att, g_att);

    // 1) QKV projection: [2048,3584] x [8192,3584]^T -> [2048,8192]
    gemm_abt_tf32<<<dim3(SEQ / 128, QKVN / 128), 256>>>(hidden, qkv_w, qkv,
                                                        SEQ, QKVN, HID);
    // 2) RoPE on q+k heads, + q scaling
    rope_kernel<<<(SEQ * 24 * 128) / 256, 256>>>(qkv, fcos, fsin);
    // 3) softcapped causal flash attention
    attn_kernel<<<dim3(SEQ / 64, NH), 256, SMEM_ATT>>>();
    // 4) output projection: [2048,4096] x [3584,4096]^T -> [2048,3584]
    gemm_abt_tf32<<<dim3(SEQ / 128, HID / 128), 256>>>(att, o_w, out,
                                                       SEQ, HID, ATTN);
}

// round 3
// speedup vs baseline: 1.1532x; 1.1213x over previous
#include <cuda_runtime.h>
#include <cuda_bf16.h>
#include <cstdint>
#include <cstddef>

// Problem constants
#define SEQ   2048
#define HID   3584
#define NH    16
#define NKV   8
#define HD    256
#define QKVN  8192            // (16 + 2*8) * 256
#define ATTN  4096            // 16 * 256
#define SCAL  0.0625f         // 256^-0.5

// Scratch (allocation-free rule: device globals)
__device__ float g_qkv[(size_t)SEQ * QKVN];   // 64 MB
__device__ float g_att[(size_t)SEQ * ATTN];   // 32 MB

// ---------------------------------------------------------------------------
// helpers
// ---------------------------------------------------------------------------
__device__ __forceinline__ unsigned f2tf32(float x) {
    unsigned r;
    asm("cvt.rna.tf32.f32 %0, %1;" : "=r"(r) : "f"(x));
    return r;
}

__device__ __forceinline__ void mma_tf32(float* d, const unsigned* a,
                                         const unsigned* b, const float* c) {
    asm volatile(
        "mma.sync.aligned.m16n8k8.row.col.f32.tf32.tf32.f32 "
        "{%0,%1,%2,%3}, {%4,%5,%6,%7}, {%8,%9}, {%10,%11,%12,%13};\n"
        : "=f"(d[0]), "=f"(d[1]), "=f"(d[2]), "=f"(d[3])
        : "r"(a[0]), "r"(a[1]), "r"(a[2]), "r"(a[3]),
          "r"(b[0]), "r"(b[1]),
          "f"(c[0]), "f"(c[1]), "f"(c[2]), "f"(c[3]));
}

__device__ __forceinline__ void cp16(unsigned smem_addr, const void* gptr) {
    asm volatile("cp.async.cg.shared.global [%0], [%1], 16;\n"
                 :: "r"(smem_addr), "l"(gptr));
}
__device__ __forceinline__ void cp_commit() {
    asm volatile("cp.async.commit_group;\n");
}
__device__ __forceinline__ void cp_wait_all() {
    asm volatile("cp.async.wait_group 0;\n");
}

// ---------------------------------------------------------------------------
// GEMM: C[M,N] = A[M,K] * B[N,K]^T   (both operands row-major, K contiguous)
// 128x128 block tile, BK=16, 256 threads, 8 warps in 2x4 (warp tile 64x32).
// ---------------------------------------------------------------------------
#define GLDA 20   // padded smem row stride (16 + 4) -> conflict-free frag loads

__global__ void __launch_bounds__(256)
gemm_abt_tf32(const float* __restrict__ A, const float* __restrict__ B,
              float* __restrict__ C, int M, int N, int K) {
    __shared__ unsigned As[2][128 * GLDA];
    __shared__ unsigned Bs[2][128 * GLDA];

    const int tid  = threadIdx.x;
    const int m0   = blockIdx.x * 128;
    const int n0   = blockIdx.y * 128;
    const int wid  = tid >> 5;
    const int lane = tid & 31;
    const int wm   = (wid >> 2) * 64;   // 0 / 64
    const int wn   = (wid & 3) * 32;    // 0..96
    const int tg   = lane >> 2;         // 0..7
    const int tq   = lane & 3;          // 0..3

    float acc[4][4][4];
#pragma unroll
    for (int mi = 0; mi < 4; mi++)
#pragma unroll
        for (int ni = 0; ni < 4; ni++)
#pragma unroll
            for (int e = 0; e < 4; e++) acc[mi][ni][e] = 0.f;

    const int lr = tid >> 2;           // 0..63 (two row passes: lr, lr+64)
    const int lc = (tid & 3) * 4;      // 0,4,8,12
    const float* pA = A + (size_t)(m0 + lr) * K + lc;
    const float* pB = B + (size_t)(n0 + lr) * K + lc;
    const int NK = K >> 4;

    // initial tile -> smem buf 0
    {
        float4 a0 = *(const float4*)pA;
        float4 a1 = *(const float4*)(pA + (size_t)64 * K);
        float4 b0 = *(const float4*)pB;
        float4 b1 = *(const float4*)(pB + (size_t)64 * K);
        unsigned* da0 = &As[0][lr * GLDA + lc];
        unsigned* da1 = &As[0][(lr + 64) * GLDA + lc];
        unsigned* db0 = &Bs[0][lr * GLDA + lc];
        unsigned* db1 = &Bs[0][(lr + 64) * GLDA + lc];
        da0[0]=f2tf32(a0.x); da0[1]=f2tf32(a0.y); da0[2]=f2tf32(a0.z); da0[3]=f2tf32(a0.w);
        da1[0]=f2tf32(a1.x); da1[1]=f2tf32(a1.y); da1[2]=f2tf32(a1.z); da1[3]=f2tf32(a1.w);
        db0[0]=f2tf32(b0.x); db0[1]=f2tf32(b0.y); db0[2]=f2tf32(b0.z); db0[3]=f2tf32(b0.w);
        db1[0]=f2tf32(b1.x); db1[1]=f2tf32(b1.y); db1[2]=f2tf32(b1.z); db1[3]=f2tf32(b1.w);
    }
    __syncthreads();

    for (int kt = 0; kt < NK; ++kt) {
        const int buf = kt & 1;
        float4 na0, na1, nb0, nb1;
        const bool more = (kt + 1 < NK);
        if (more) {
            const float* qA = pA + (size_t)(kt + 1) * 16;
            const float* qB = pB + (size_t)(kt + 1) * 16;
            na0 = *(const float4*)qA;
            na1 = *(const float4*)(qA + (size_t)64 * K);
            nb0 = *(const float4*)qB;
            nb1 = *(const float4*)(qB + (size_t)64 * K);
        }
#pragma unroll
        for (int kk = 0; kk < 16; kk += 8) {
            unsigned af[4][4], bf[4][2];
#pragma unroll
            for (int mi = 0; mi < 4; mi++) {
                const int r = wm + mi * 16 + tg;
                af[mi][0] = As[buf][r * GLDA + kk + tq];
                af[mi][1] = As[buf][(r + 8) * GLDA + kk + tq];
                af[mi][2] = As[buf][r * GLDA + kk + tq + 4];
                af[mi][3] = As[buf][(r + 8) * GLDA + kk + tq + 4];
            }
#pragma unroll
            for (int ni = 0; ni < 4; ni++) {
                const int r = wn + ni * 8 + tg;
                bf[ni][0] = Bs[buf][r * GLDA + kk + tq];
                bf[ni][1] = Bs[buf][r * GLDA + kk + tq + 4];
            }
#pragma unroll
            for (int mi = 0; mi < 4; mi++)
#pragma unroll
                for (int ni = 0; ni < 4; ni++)
                    mma_tf32(acc[mi][ni], af[mi], bf[ni], acc[mi][ni]);
        }
        if (more) {
            const int nb = buf ^ 1;
            unsigned* da0 = &As[nb][lr * GLDA + lc];
            unsigned* da1 = &As[nb][(lr + 64) * GLDA + lc];
            unsigned* db0 = &Bs[nb][lr * GLDA + lc];
            unsigned* db1 = &Bs[nb][(lr + 64) * GLDA + lc];
            da0[0]=f2tf32(na0.x); da0[1]=f2tf32(na0.y); da0[2]=f2tf32(na0.z); da0[3]=f2tf32(na0.w);
            da1[0]=f2tf32(na1.x); da1[1]=f2tf32(na1.y); da1[2]=f2tf32(na1.z); da1[3]=f2tf32(na1.w);
            db0[0]=f2tf32(nb0.x); db0[1]=f2tf32(nb0.y); db0[2]=f2tf32(nb0.z); db0[3]=f2tf32(nb0.w);
            db1[0]=f2tf32(nb1.x); db1[1]=f2tf32(nb1.y); db1[2]=f2tf32(nb1.z); db1[3]=f2tf32(nb1.w);
        }
        __syncthreads();
    }

    // epilogue
#pragma unroll
    for (int mi = 0; mi < 4; mi++) {
#pragma unroll
        for (int ni = 0; ni < 4; ni++) {
            const int r = m0 + wm + mi * 16 + tg;
            const int c = n0 + wn + ni * 8 + tq * 2;
            float2 v0 = make_float2(acc[mi][ni][0], acc[mi][ni][1]);
            float2 v1 = make_float2(acc[mi][ni][2], acc[mi][ni][3]);
            *(float2*)&C[(size_t)r * N + c]       = v0;
            *(float2*)&C[(size_t)(r + 8) * N + c] = v1;
        }
    }
}

// ---------------------------------------------------------------------------
// RoPE + q-scaling + tf32 pre-conversion on q/k columns [0, 6144)
// ---------------------------------------------------------------------------
__global__ void rope_conv_kernel(float* __restrict__ qkv,
                                 const float* __restrict__ fcos,
                                 const float* __restrict__ fsin) {
    const int idx = blockIdx.x * blockDim.x + threadIdx.x;   // exact multiple
    const int d = idx & 127;
    const int h = (idx >> 7) % 24;
    const int s = idx / (24 * 128);
    const size_t base = (size_t)s * QKVN + h * 256;
    float xr = qkv[base + d];
    float xi = qkv[base + 128 + d];
    const float c  = fcos[s * 128 + d];
    const float sn = fsin[s * 128 + d];
    float nr = xr * c - xi * sn;
    float ni = xr * sn + xi * c;
    if (h < NH) { nr *= SCAL; ni *= SCAL; }
    qkv[base + d]       = __uint_as_float(f2tf32(nr));
    qkv[base + 128 + d] = __uint_as_float(f2tf32(ni));
}

// tf32 pre-conversion of v columns [6144, 8192)
__global__ void vconv_kernel(float* __restrict__ qkv) {
    const int idx = blockIdx.x * blockDim.x + threadIdx.x;   // SEQ*512 threads
    const int s = idx >> 9;
    const int c = (idx & 511) * 4;
    float4* p = (float4*)&qkv[(size_t)s * QKVN + 6144 + c];
    float4 v = *p;
    v.x = __uint_as_float(f2tf32(v.x));
    v.y = __uint_as_float(f2tf32(v.y));
    v.z = __uint_as_float(f2tf32(v.z));
    v.w = __uint_as_float(f2tf32(v.w));
    *p = v;
}

// ---------------------------------------------------------------------------
// Flash attention with tanh softcap, v3.
// - g_qkv is pre-converted to tf32 bit patterns -> loads are cp.async copies.
// - Fixed softmax shift (scores capped to [-50,50]): p = exp(50*tanh(s/50)-50)
//   = exp(-100/(exp(s/25)+1)). No online max/sum, no O rescaling; row sums
//   accumulated per-thread, reduced once at the end.
// Block: 256 threads (8 warps): band=wid>>1 owns 16 q-rows; chalf=wid&1 owns
//   a 32-col half of S and a 128-d half of O.
// ---------------------------------------------------------------------------
#define LDQ 260   // 256 + 4 pad (1040 B row stride, 16B-aligned)
#define LDP 68    // 64 + 4 pad
// words: 3*64*LDQ (Q,K,V) + 64*LDP (P) + 128 (lsum)
#define SMEM_ATT ((3 * 64 * LDQ + 64 * LDP + 128) * 4)   // 217600 bytes

__global__ void __launch_bounds__(256)
attn_kernel() {
    extern __shared__ unsigned sm[];
    unsigned* Qs = sm;
    unsigned* Ks = Qs + 64 * LDQ;
    unsigned* Vs = Ks + 64 * LDQ;
    unsigned* Ps = Vs + 64 * LDQ;
    float* lsum = (float*)(Ps + 64 * LDP);   // [2][64]

    const unsigned sb  = (unsigned)__cvta_generic_to_shared(sm);
    const unsigned ksb = sb + 64 * LDQ * 4;
    const unsigned vsb = sb + 2 * 64 * LDQ * 4;

    const int tid   = threadIdx.x;
    const int wid   = tid >> 5;
    const int lane  = tid & 31;
    const int tg    = lane >> 2;
    const int tq    = lane & 3;
    const int band  = wid >> 1;       // 0..3
    const int chalf = wid & 1;        // 0..1
    const int wm    = band * 16;

    const int qt = (int)(gridDim.x - 1) - (int)blockIdx.x;  // heavy tiles first
    const int q0 = qt * 64;
    const int h  = blockIdx.y;
    const int kh = h >> 1;
    const int qcb = h * 256;
    const int kcb = 4096 + kh * 256;
    const int vcb = 6144 + kh * 256;

    // Q tile via cp.async (already tf32 bit patterns)
    for (int i = tid; i < 64 * 64; i += 256) {
        const int r = i >> 6, c4 = (i & 63) * 4;
        cp16(sb + (unsigned)(r * LDQ + c4) * 4,
             &g_qkv[(size_t)(q0 + r) * QKVN + qcb + c4]);
    }
    cp_commit();

    float o[16][4];
#pragma unroll
    for (int nf = 0; nf < 16; nf++)
#pragma unroll
        for (int e = 0; e < 4; e++) o[nf][e] = 0.f;
    float lp0 = 0.f, lp1 = 0.f;

    const int cb = chalf * 32;    // S-column base for this warp
    const int db = chalf * 128;   // O d-column base for this warp

    for (int kt = 0; kt <= qt; ++kt) {
        __syncthreads();   // everyone done reading prev K/V/P
        const int r0g = kt * 64;
        for (int i = tid; i < 64 * 64; i += 256) {
            const int r = i >> 6, c4 = (i & 63) * 4;
            const size_t rowb = (size_t)(r0g + r) * QKVN;
            const unsigned off = (unsigned)(r * LDQ + c4) * 4;
            cp16(ksb + off, &g_qkv[rowb + kcb + c4]);
            cp16(vsb + off, &g_qkv[rowb + vcb + c4]);
        }
        cp_commit();
        cp_wait_all();
        __syncthreads();

        // S = Q K^T  (16 rows x 32 cols per warp)
        float s[4][4];
#pragma unroll
        for (int nf = 0; nf < 4; nf++)
#pragma unroll
            for (int e = 0; e < 4; e++) s[nf][e] = 0.f;

        for (int ks = 0; ks < 32; ++ks) {
            const int kk = ks * 8;
            unsigned a[4];
            const int ra = (wm + tg) * LDQ + kk + tq;
            a[0] = Qs[ra];
            a[1] = Qs[ra + 8 * LDQ];
            a[2] = Qs[ra + 4];
            a[3] = Qs[ra + 8 * LDQ + 4];
#pragma unroll
            for (int nf = 0; nf < 4; nf++) {
                unsigned b[2];
                const int rb = (cb + nf * 8 + tg) * LDQ + kk + tq;
                b[0] = Ks[rb];
                b[1] = Ks[rb + 4];
                mma_tf32(s[nf], a, b, s[nf]);
            }
        }

        // softcap + fixed-shift exp + causal mask; accumulate row sums
        const bool diag = (kt == qt);
        const int grow0 = q0 + wm + tg;
#pragma unroll
        for (int nf = 0; nf < 4; nf++) {
#pragma unroll
            for (int e = 0; e < 4; e++) {
                const float x = s[nf][e];
                const float ex = __expf(x * 0.04f);            // e^{x/25}
                float p = __expf(__fdividef(-100.f, ex + 1.f)); // e^{50tanh(x/50)-50}
                if (diag) {
                    const int col = kt * 64 + cb + nf * 8 + tq * 2 + (e & 1);
                    const int row = grow0 + ((e >> 1) << 3);
                    if (col > row) p = 0.f;
                }
                if (e < 2) lp0 += p; else lp1 += p;
                const int prow = wm + tg + ((e >> 1) << 3);
                Ps[prow * LDP + cb + nf * 8 + tq * 2 + (e & 1)] = f2tf32(p);
            }
        }
        __syncthreads();   // P visible to both chalf warps

        // O += P V   (16 rows x 128 d-cols per warp, k = 64)
#pragma unroll
        for (int ks = 0; ks < 8; ++ks) {
            const int kk = ks * 8;
            unsigned a[4];
            const int ra = (wm + tg) * LDP + kk + tq;
            a[0] = Ps[ra];
            a[1] = Ps[ra + 8 * LDP];
            a[2] = Ps[ra + 4];
            a[3] = Ps[ra + 8 * LDP + 4];
#pragma unroll
            for (int nf = 0; nf < 16; nf++) {
                unsigned b[2];
                const int rb = (kk + tq) * LDQ + db + nf * 8 + tg;
                b[0] = Vs[rb];
                b[1] = Vs[rb + 4 * LDQ];
                mma_tf32(o[nf], a, b, o[nf]);
            }
        }
    }

    // final row-sum reduction: over tq lanes, then across chalf warps
    lp0 += __shfl_xor_sync(0xffffffffu, lp0, 1);
    lp0 += __shfl_xor_sync(0xffffffffu, lp0, 2);
    lp1 += __shfl_xor_sync(0xffffffffu, lp1, 1);
    lp1 += __shfl_xor_sync(0xffffffffu, lp1, 2);
    if (tq == 0) {
        lsum[chalf * 64 + wm + tg]     = lp0;
        lsum[chalf * 64 + wm + tg + 8] = lp1;
    }
    __syncthreads();
    const float i0 = 1.f / (lsum[wm + tg]     + lsum[64 + wm + tg]);
    const float i1 = 1.f / (lsum[wm + tg + 8] + lsum[64 + wm + tg + 8]);

    const size_t r0 = (size_t)(q0 + wm + tg);
#pragma unroll
    for (int nf = 0; nf < 16; nf++) {
        const int c = qcb + db + nf * 8 + tq * 2;
        *(float2*)&g_att[r0 * ATTN + c]       = make_float2(o[nf][0] * i0, o[nf][1] * i0);
        *(float2*)&g_att[(r0 + 8) * ATTN + c] = make_float2(o[nf][2] * i1, o[nf][3] * i1);
    }
}

// ---------------------------------------------------------------------------
// launch
// ---------------------------------------------------------------------------
extern "C" void kernel_launch(void* const* d_in, const int* in_sizes, int n_in,
                              void* d_out, int out_size) {
    const float* hidden = (const float*)d_in[0];
    const float* fcos   = (const float*)d_in[1];
    const float* fsin   = (const float*)d_in[2];
    /* d_in[3] = mask: causal mask is generated analytically */
    const float* qkv_w  = (const float*)d_in[4];
    const float* o_w    = (const float*)d_in[5];
    float* out = (float*)d_out;

    cudaFuncSetAttribute(attn_kernel,
                         cudaFuncAttributeMaxDynamicSharedMemorySize, SMEM_ATT);

    float* qkv = nullptr;
    float* att = nullptr;
    cudaGetSymbolAddress((void**)&qkv, g_qkv);
    cudaGetSymbolAddress((void**)&att, g_att);

    // 1) QKV projection: [2048,3584] x [8192,3584]^T -> [2048,8192]
    gemm_abt_tf32<<<dim3(SEQ / 128, QKVN / 128), 256>>>(hidden, qkv_w, qkv,
                                                        SEQ, QKVN, HID);
    // 2) RoPE on q+k heads (+ q scaling) with tf32 conversion; V conversion
    rope_conv_kernel<<<(SEQ * 24 * 128) / 256, 256>>>(qkv, fcos, fsin);
    vconv_kernel<<<(SEQ * 512) / 256, 256>>>(qkv);
    // 3) softcapped causal flash attention
    attn_kernel<<<dim3(SEQ / 64, NH), 256, SMEM_ATT>>>();
    // 4) output projection: [2048,4096] x [3584,4096]^T -> [2048,3584]
    gemm_abt_tf32<<<dim3(SEQ / 128, HID / 128), 256>>>(att, o_w, out,
                                                       SEQ, HID, ATTN);
}